// round 1
// baseline (speedup 1.0000x reference)
#include <cuda_runtime.h>
#include <cstdint>

#define NB 16
#define CIN 64
#define HH 112
#define WW 112
#define COUT 128
#define QQ 3

// 51.4 MB scratch for the bilinearly shifted activations
__device__ float g_shifted[(size_t)NB * CIN * HH * WW];

// ---------------------------------------------------------------------------
// Kernel 1: per-channel bilinear shift (zero padding), exactly mirroring the
// reference's per-element floor/frac computation.
// ---------------------------------------------------------------------------
__global__ void shift_kernel(const float* __restrict__ x,
                             const float* __restrict__ shifts) {
    int tid = blockIdx.x * blockDim.x + threadIdx.x;
    const int total = NB * CIN * HH * WW;
    if (tid >= total) return;

    int j = tid % WW;
    int i = (tid / WW) % HH;
    int c = (tid / (WW * HH)) % CIN;
    int n = tid / (WW * HH * CIN);

    float sx = shifts[c * 2 + 0] * 4.0f;
    float sy = shifts[c * 2 + 1] * 4.0f;

    float jx = (float)j + sx;
    float iy = (float)i + sy;
    float x0f = floorf(jx);
    float y0f = floorf(iy);
    float wx = jx - x0f;
    float wy = iy - y0f;
    int x0 = (int)x0f;
    int y0 = (int)y0f;

    const float* xp = x + ((size_t)(n * CIN + c) * HH) * WW;

    float v00 = 0.f, v01 = 0.f, v10 = 0.f, v11 = 0.f;
    bool vy0 = (y0 >= 0) && (y0 < HH);
    bool vy1 = (y0 + 1 >= 0) && (y0 + 1 < HH);
    bool vx0 = (x0 >= 0) && (x0 < WW);
    bool vx1 = (x0 + 1 >= 0) && (x0 + 1 < WW);
    if (vy0 && vx0) v00 = xp[y0 * WW + x0];
    if (vy0 && vx1) v01 = xp[y0 * WW + x0 + 1];
    if (vy1 && vx0) v10 = xp[(y0 + 1) * WW + x0];
    if (vy1 && vx1) v11 = xp[(y0 + 1) * WW + x0 + 1];

    g_shifted[tid] = (1.f - wy) * ((1.f - wx) * v00 + wx * v01)
                   + wy * ((1.f - wx) * v10 + wx * v11);
}

// ---------------------------------------------------------------------------
// Packed f32x2 helpers (full-rate fp32 on sm_103a is only reachable via
// fma.rn.f32x2 — scalar FFMA is half-rate)
// ---------------------------------------------------------------------------
__device__ __forceinline__ unsigned long long ffma2(unsigned long long a,
                                                    unsigned long long b,
                                                    unsigned long long c) {
    unsigned long long d;
    asm("fma.rn.f32x2 %0, %1, %2, %3;" : "=l"(d) : "l"(a), "l"(b), "l"(c));
    return d;
}

__device__ __forceinline__ unsigned long long pack2(float v) {
    unsigned long long d;
    asm("mov.b64 %0, {%1, %1};" : "=l"(d) : "f"(v));
    return d;
}

// ---------------------------------------------------------------------------
// Kernel 2: fused Maclaurin-powers + 3x3 conv (direct, smem-tiled)
// Block: 16x16 output pixels, 16 output channels, 1 batch index.
// Loop over 64 input channels; powers p, p^2, p^3 computed on the fly.
// ---------------------------------------------------------------------------
__global__ void __launch_bounds__(256)
conv_kernel(const float* __restrict__ weights,
            const float* __restrict__ bias,
            float* __restrict__ out) {
    __shared__ float s_in[18 * 20];
    __shared__ __align__(16) float s_w[QQ * 9 * 16];  // [q][k][co] co fastest

    const int tid = threadIdx.x;
    const int tx = tid & 15;
    const int ty = tid >> 4;
    const int bx = blockIdx.x % 7;
    const int by = blockIdx.x / 7;
    const int w0 = bx * 16;
    const int h0 = by * 16;
    const int co_base = blockIdx.y * 16;
    const int n = blockIdx.z;

    unsigned long long acc[8];
#pragma unroll
    for (int g = 0; g < 8; ++g) acc[g] = 0ULL;  // (0.f, 0.f)

    for (int ci = 0; ci < CIN; ++ci) {
        __syncthreads();  // protect previous iteration's smem reads

        // ---- stage weights for this ci: 16 co * 3 q * 9 taps = 432 floats
        {
            int idx = tid;
            {
                int co = idx / 27;
                int r = idx - co * 27;
                int q = r / 9;
                int k = r - q * 9;
                s_w[(q * 9 + k) * 16 + co] =
                    weights[((size_t)(co_base + co) * (QQ * CIN) + q * CIN + ci) * 9 + k];
            }
            idx = tid + 256;
            if (idx < 432) {
                int co = idx / 27;
                int r = idx - co * 27;
                int q = r / 9;
                int k = r - q * 9;
                s_w[(q * 9 + k) * 16 + co] =
                    weights[((size_t)(co_base + co) * (QQ * CIN) + q * CIN + ci) * 9 + k];
            }
        }

        // ---- stage 18x18 input halo tile of shifted channel ci
        {
            const float* sp = g_shifted + ((size_t)(n * CIN + ci) * HH) * WW;
            int idx = tid;  // always < 324
            {
                int r = idx / 18;
                int cc = idx - r * 18;
                int gh = h0 - 1 + r;
                int gw = w0 - 1 + cc;
                float v = 0.f;
                if (gh >= 0 && gh < HH && gw >= 0 && gw < WW) v = sp[gh * WW + gw];
                s_in[r * 20 + cc] = v;
            }
            idx = tid + 256;
            if (idx < 324) {
                int r = idx / 18;
                int cc = idx - r * 18;
                int gh = h0 - 1 + r;
                int gw = w0 - 1 + cc;
                float v = 0.f;
                if (gh >= 0 && gh < HH && gw >= 0 && gw < WW) v = sp[gh * WW + gw];
                s_in[r * 20 + cc] = v;
            }
        }
        __syncthreads();

        // ---- accumulate: 9 taps x 3 powers x 16 co (as 8 f32x2 pairs)
#pragma unroll
        for (int k = 0; k < 9; ++k) {
            const int dy = k / 3;
            const int dx = k % 3;
            float p1 = s_in[(ty + dy) * 20 + (tx + dx)];
            float p2 = p1 * p1;
            float p3 = p2 * p1;
            unsigned long long pp[3];
            pp[0] = pack2(p1);
            pp[1] = pack2(p2);
            pp[2] = pack2(p3);
#pragma unroll
            for (int q = 0; q < 3; ++q) {
                const ulonglong2* wrow =
                    (const ulonglong2*)&s_w[(q * 9 + k) * 16];
#pragma unroll
                for (int g = 0; g < 4; ++g) {
                    ulonglong2 wv = wrow[g];
                    acc[2 * g + 0] = ffma2(wv.x, pp[q], acc[2 * g + 0]);
                    acc[2 * g + 1] = ffma2(wv.y, pp[q], acc[2 * g + 1]);
                }
            }
        }
    }

    // ---- epilogue: add bias, write 16 output channels
    const int opix = (h0 + ty) * WW + (w0 + tx);
    float* op = out + ((size_t)n * COUT + co_base) * (HH * WW) + opix;
#pragma unroll
    for (int j = 0; j < 8; ++j) {
        float lo = __uint_as_float((unsigned)(acc[j] & 0xffffffffULL));
        float hi = __uint_as_float((unsigned)(acc[j] >> 32));
        op[(size_t)(2 * j + 0) * (HH * WW)] = lo + bias[co_base + 2 * j + 0];
        op[(size_t)(2 * j + 1) * (HH * WW)] = hi + bias[co_base + 2 * j + 1];
    }
}

// ---------------------------------------------------------------------------
extern "C" void kernel_launch(void* const* d_in, const int* in_sizes, int n_in,
                              void* d_out, int out_size) {
    const float* x = (const float*)d_in[0];
    const float* weights = (const float*)d_in[1];
    const float* bias = (const float*)d_in[2];
    const float* shifts = (const float*)d_in[3];
    float* out = (float*)d_out;

    const int total = NB * CIN * HH * WW;
    shift_kernel<<<(total + 255) / 256, 256>>>(x, shifts);

    dim3 grid(7 * 7, COUT / 16, NB);
    conv_kernel<<<grid, 256>>>(weights, bias, out);
}

// round 2
// speedup vs baseline: 1.3915x; 1.3915x over previous
#include <cuda_runtime.h>
#include <cstdint>

#define NB 16
#define CIN 64
#define HH 112
#define WW 112
#define COUT 128
#define QQ 3

// 51.4 MB scratch for the bilinearly shifted activations
__device__ float g_shifted[(size_t)NB * CIN * HH * WW];
// transposed weights: [ci][q*9+k][co]  (co fastest, coalesced staging)
__device__ float g_wt[(size_t)CIN * 27 * COUT];

// ---------------------------------------------------------------------------
// Kernel 1: per-channel bilinear shift (zero padding)
// ---------------------------------------------------------------------------
__global__ void shift_kernel(const float* __restrict__ x,
                             const float* __restrict__ shifts) {
    int tid = blockIdx.x * blockDim.x + threadIdx.x;
    const int total = NB * CIN * HH * WW;
    if (tid >= total) return;

    int j = tid % WW;
    int i = (tid / WW) % HH;
    int c = (tid / (WW * HH)) % CIN;
    int n = tid / (WW * HH * CIN);

    float sx = shifts[c * 2 + 0] * 4.0f;
    float sy = shifts[c * 2 + 1] * 4.0f;

    float jx = (float)j + sx;
    float iy = (float)i + sy;
    float x0f = floorf(jx);
    float y0f = floorf(iy);
    float wx = jx - x0f;
    float wy = iy - y0f;
    int x0 = (int)x0f;
    int y0 = (int)y0f;

    const float* xp = x + ((size_t)(n * CIN + c) * HH) * WW;

    float v00 = 0.f, v01 = 0.f, v10 = 0.f, v11 = 0.f;
    bool vy0 = (y0 >= 0) && (y0 < HH);
    bool vy1 = (y0 + 1 >= 0) && (y0 + 1 < HH);
    bool vx0 = (x0 >= 0) && (x0 < WW);
    bool vx1 = (x0 + 1 >= 0) && (x0 + 1 < WW);
    if (vy0 && vx0) v00 = xp[y0 * WW + x0];
    if (vy0 && vx1) v01 = xp[y0 * WW + x0 + 1];
    if (vy1 && vx0) v10 = xp[(y0 + 1) * WW + x0];
    if (vy1 && vx1) v11 = xp[(y0 + 1) * WW + x0 + 1];

    g_shifted[tid] = (1.f - wy) * ((1.f - wx) * v00 + wx * v01)
                   + wy * ((1.f - wx) * v10 + wx * v11);
}

// ---------------------------------------------------------------------------
// Kernel 1b: one-time weight transpose into [ci][qk][co]
// ---------------------------------------------------------------------------
__global__ void wt_kernel(const float* __restrict__ w) {
    int idx = blockIdx.x * blockDim.x + threadIdx.x;
    const int total = CIN * 27 * COUT;
    if (idx >= total) return;
    int co = idx % COUT;
    int qk = (idx / COUT) % 27;
    int ci = idx / (COUT * 27);
    int q = qk / 9;
    int k = qk - q * 9;
    g_wt[idx] = w[((size_t)co * (QQ * CIN) + q * CIN + ci) * 9 + k];
}

// ---------------------------------------------------------------------------
// Packed f32x2 helpers
// ---------------------------------------------------------------------------
__device__ __forceinline__ unsigned long long ffma2(unsigned long long a,
                                                    unsigned long long b,
                                                    unsigned long long c) {
    unsigned long long d;
    asm("fma.rn.f32x2 %0, %1, %2, %3;" : "=l"(d) : "l"(a), "l"(b), "l"(c));
    return d;
}

__device__ __forceinline__ unsigned long long mul2(unsigned long long a,
                                                   unsigned long long b) {
    unsigned long long d;
    asm("mul.rn.f32x2 %0, %1, %2;" : "=l"(d) : "l"(a), "l"(b));
    return d;
}

__device__ __forceinline__ unsigned long long pack2(float v) {
    unsigned long long d;
    asm("mov.b64 %0, {%1, %1};" : "=l"(d) : "f"(v));
    return d;
}

// ---------------------------------------------------------------------------
// Kernel 2: fused Maclaurin-powers + 3x3 conv, FMA-pipe bound.
// Block: 256 threads = (8x8 spatial threads, each 2x2 pixels) x 4 co-groups.
// Block tile: 16x16 pixels x 64 output channels x 1 batch.
// Per thread: 4 pixels x 16 co = 32 f32x2 accumulators.
// ---------------------------------------------------------------------------
__global__ void __launch_bounds__(256, 1)
conv_kernel(const float* __restrict__ bias, float* __restrict__ out) {
    __shared__ float s_in[18][20];
    __shared__ __align__(16) float s_w[27][64];

    const int tid = threadIdx.x;
    const int tx = tid & 7;
    const int ty = (tid >> 3) & 7;
    const int cg = tid >> 6;              // 0..3 (warp-uniform)
    const int bx = blockIdx.x % 7;
    const int by = blockIdx.x / 7;
    const int w0 = bx * 16;
    const int h0 = by * 16;
    const int co_half = blockIdx.y;       // 0..1
    const int n = blockIdx.z;
    const int co_base = co_half * 64 + cg * 16;

    unsigned long long acc[32];
#pragma unroll
    for (int i = 0; i < 32; ++i) acc[i] = 0ULL;

    for (int ci = 0; ci < CIN; ++ci) {
        __syncthreads();  // protect previous iteration's smem reads

        // ---- stage weights: 27*64 = 1728 floats, fully coalesced
        {
            const float* wsrc = g_wt + (size_t)ci * 27 * COUT + co_half * 64;
#pragma unroll
            for (int i = 0; i < 7; ++i) {
                int idx = i * 256 + tid;
                if (idx < 1728) {
                    int r = idx >> 6;
                    int c = idx & 63;
                    s_w[r][c] = wsrc[(size_t)r * COUT + c];
                }
            }
        }

        // ---- stage 18x18 input halo tile of shifted channel ci
        {
            const float* sp = g_shifted + ((size_t)(n * CIN + ci) * HH) * WW;
#pragma unroll
            for (int i = 0; i < 2; ++i) {
                int idx = i * 256 + tid;
                if (idx < 324) {
                    int r = idx / 18;
                    int c = idx - r * 18;
                    int gh = h0 - 1 + r;
                    int gw = w0 - 1 + c;
                    float v = 0.f;
                    if (gh >= 0 && gh < HH && gw >= 0 && gw < WW)
                        v = sp[gh * WW + gw];
                    s_in[r][c] = v;
                }
            }
        }
        __syncthreads();

        // ---- accumulate
#pragma unroll
        for (int dy = 0; dy < 3; ++dy) {
            const int ra = 2 * ty + dy;
            // 2 rows x 4 cols region needed for this tap row
            float2 a01 = *(const float2*)&s_in[ra][2 * tx];
            float2 a23 = *(const float2*)&s_in[ra][2 * tx + 2];
            float2 b01 = *(const float2*)&s_in[ra + 1][2 * tx];
            float2 b23 = *(const float2*)&s_in[ra + 1][2 * tx + 2];
            float va[4] = {a01.x, a01.y, a23.x, a23.y};
            float vb[4] = {b01.x, b01.y, b23.x, b23.y};

            unsigned long long pa[3][4], pb[3][4];
#pragma unroll
            for (int c = 0; c < 4; ++c) {
                pa[0][c] = pack2(va[c]);
                pb[0][c] = pack2(vb[c]);
                pa[1][c] = mul2(pa[0][c], pa[0][c]);
                pb[1][c] = mul2(pb[0][c], pb[0][c]);
                pa[2][c] = mul2(pa[1][c], pa[0][c]);
                pb[2][c] = mul2(pb[1][c], pb[0][c]);
            }

#pragma unroll
            for (int dx = 0; dx < 3; ++dx) {
#pragma unroll
                for (int q = 0; q < 3; ++q) {
                    const ulonglong2* wr =
                        (const ulonglong2*)&s_w[q * 9 + dy * 3 + dx][cg * 16];
                    ulonglong2 w01 = wr[0];
                    ulonglong2 w23 = wr[1];
                    ulonglong2 w45 = wr[2];
                    ulonglong2 w67 = wr[3];
                    unsigned long long wv[8] = {w01.x, w01.y, w23.x, w23.y,
                                                w45.x, w45.y, w67.x, w67.y};
#pragma unroll
                    for (int py = 0; py < 2; ++py) {
#pragma unroll
                        for (int px = 0; px < 2; ++px) {
                            unsigned long long p =
                                py ? pb[q][px + dx] : pa[q][px + dx];
                            unsigned long long* a = &acc[(py * 2 + px) * 8];
#pragma unroll
                            for (int j = 0; j < 8; ++j)
                                a[j] = ffma2(wv[j], p, a[j]);
                        }
                    }
                }
            }
        }
    }

    // ---- epilogue: add bias, write 4 px x 16 co
#pragma unroll
    for (int py = 0; py < 2; ++py) {
#pragma unroll
        for (int px = 0; px < 2; ++px) {
            int y = h0 + 2 * ty + py;
            int x = w0 + 2 * tx + px;
            float* op = out + (((size_t)n * COUT + co_base) * HH + y) * WW + x;
#pragma unroll
            for (int j = 0; j < 8; ++j) {
                unsigned long long a = acc[(py * 2 + px) * 8 + j];
                float lo = __uint_as_float((unsigned)(a & 0xffffffffULL));
                float hi = __uint_as_float((unsigned)(a >> 32));
                op[(size_t)(2 * j + 0) * (HH * WW)] =
                    lo + bias[co_base + 2 * j + 0];
                op[(size_t)(2 * j + 1) * (HH * WW)] =
                    hi + bias[co_base + 2 * j + 1];
            }
        }
    }
}

// ---------------------------------------------------------------------------
extern "C" void kernel_launch(void* const* d_in, const int* in_sizes, int n_in,
                              void* d_out, int out_size) {
    const float* x = (const float*)d_in[0];
    const float* weights = (const float*)d_in[1];
    const float* bias = (const float*)d_in[2];
    const float* shifts = (const float*)d_in[3];
    float* out = (float*)d_out;

    const int total = NB * CIN * HH * WW;
    shift_kernel<<<(total + 255) / 256, 256>>>(x, shifts);

    const int wtotal = CIN * 27 * COUT;
    wt_kernel<<<(wtotal + 255) / 256, 256>>>(weights);

    dim3 grid(7 * 7, 2, NB);
    conv_kernel<<<grid, 256>>>(bias, out);
}

// round 4
// speedup vs baseline: 4.4136x; 3.1719x over previous
#include <cuda_runtime.h>
#include <cstdint>

#define NB 16
#define CIN 64
#define HH 112
#define WW 112
#define COUT 128
#define HP 114                       // padded spatial (1-pixel halo)
#define HP2 (HP * HP)                // 12996
#define MPAD (NB * HP2)              // 207936 GEMM rows
#define KPT 192                      // K per tap (3 powers x 64 ci)
#define KTOT 1728                    // 9 taps * 192
#define NCHUNK 108                   // 1728 / 16
#define STAGES 3
#define PITCH 20                     // floats per smem tile row (80B, 16B-aligned)
#define TILE_F (128 * PITCH)         // floats per A or B tile
#define STAGE_F (2 * TILE_F)
#define SMEM_BYTES (STAGES * STAGE_F * 4)  // 61440

// scratch: padded tf32 powers matrix and tf32 weight matrix (16B aligned for cp.async)
__device__ __align__(128) float g_P[(size_t)MPAD * KPT];   // [m][q*64+ci]
__device__ __align__(128) float g_B[(size_t)COUT * KTOT];  // [co][tap*192+q*64+ci]

// ---------------------------------------------------------------------------
// PTX helpers (base PTX only — target is sm_103 family, no tcgen05.ld there)
// ---------------------------------------------------------------------------
__device__ __forceinline__ uint32_t smem_u32(const void* p) {
    uint32_t a;
    asm("{ .reg .u64 t; cvta.to.shared.u64 t, %1; cvt.u32.u64 %0, t; }"
        : "=r"(a) : "l"(p));
    return a;
}

__device__ __forceinline__ void cp16(uint32_t dst, const void* src, uint32_t sz) {
    asm volatile("cp.async.cg.shared.global [%0], [%1], 16, %2;"
                 :: "r"(dst), "l"(src), "r"(sz) : "memory");
}

#define CP_COMMIT() asm volatile("cp.async.commit_group;" ::: "memory")
#define CP_WAIT1()  asm volatile("cp.async.wait_group 1;" ::: "memory")

#define LDSM_X4(r0, r1, r2, r3, addr)                                         \
    asm volatile("ldmatrix.sync.aligned.m8n8.x4.shared.b16 {%0,%1,%2,%3}, [%4];" \
                 : "=r"(r0), "=r"(r1), "=r"(r2), "=r"(r3) : "r"(addr))

#define LDSM_X2(r0, r1, addr)                                                 \
    asm volatile("ldmatrix.sync.aligned.m8n8.x2.shared.b16 {%0,%1}, [%2];"    \
                 : "=r"(r0), "=r"(r1) : "r"(addr))

#define MMA_TF32(c, a0, a1, a2, a3, b0, b1)                                   \
    asm volatile(                                                             \
        "mma.sync.aligned.m16n8k8.row.col.f32.tf32.tf32.f32 "                 \
        "{%0,%1,%2,%3}, {%4,%5,%6,%7}, {%8,%9}, {%0,%1,%2,%3};"               \
        : "+f"((c)[0]), "+f"((c)[1]), "+f"((c)[2]), "+f"((c)[3])              \
        : "r"(a0), "r"(a1), "r"(a2), "r"(a3), "r"(b0), "r"(b1))

__device__ __forceinline__ float round_tf32(float v) {
    uint32_t t;
    asm("cvt.rna.tf32.f32 %0, %1;" : "=r"(t) : "f"(v));
    return __uint_as_float(t);
}

// ---------------------------------------------------------------------------
// Kernel 1: fused bilinear shift + Maclaurin powers into padded tf32 matrix P
// ---------------------------------------------------------------------------
__global__ void __launch_bounds__(256)
pbuild_kernel(const float* __restrict__ x, const float* __restrict__ shifts) {
    __shared__ float sv[CIN][HP + 6];
    const int tid = threadIdx.x;
    const int hp = blockIdx.x % HP;
    const int n = blockIdx.x / HP;

    for (int idx = tid; idx < CIN * HP; idx += 256) {
        int ci = idx / HP;
        int wp = idx % HP;
        float v = 0.f;
        if (hp >= 1 && hp <= HH && wp >= 1 && wp <= WW) {
            int h = hp - 1, w = wp - 1;
            float sx = shifts[ci * 2 + 0] * 4.0f;
            float sy = shifts[ci * 2 + 1] * 4.0f;
            float jx = (float)w + sx;
            float iy = (float)h + sy;
            float x0f = floorf(jx);
            float y0f = floorf(iy);
            float wx = jx - x0f;
            float wy = iy - y0f;
            int x0 = (int)x0f;
            int y0 = (int)y0f;
            const float* xp = x + ((size_t)(n * CIN + ci) * HH) * WW;
            float v00 = 0.f, v01 = 0.f, v10 = 0.f, v11 = 0.f;
            bool vy0 = (y0 >= 0) && (y0 < HH);
            bool vy1 = (y0 + 1 >= 0) && (y0 + 1 < HH);
            bool vx0 = (x0 >= 0) && (x0 < WW);
            bool vx1 = (x0 + 1 >= 0) && (x0 + 1 < WW);
            if (vy0 && vx0) v00 = xp[y0 * WW + x0];
            if (vy0 && vx1) v01 = xp[y0 * WW + x0 + 1];
            if (vy1 && vx0) v10 = xp[(y0 + 1) * WW + x0];
            if (vy1 && vx1) v11 = xp[(y0 + 1) * WW + x0 + 1];
            v = (1.f - wy) * ((1.f - wx) * v00 + wx * v01)
              + wy * ((1.f - wx) * v10 + wx * v11);
        }
        sv[ci][wp] = v;
    }
    __syncthreads();

    const size_t base = (size_t)blockIdx.x * HP * KPT;
    for (int idx = tid; idx < HP * KPT; idx += 256) {
        int wp = idx / KPT;
        int k = idx % KPT;
        int q = k >> 6;
        int ci = k & 63;
        float v = sv[ci][wp];
        float p = (q == 0) ? v : (q == 1 ? v * v : v * v * v);
        g_P[base + idx] = round_tf32(p);
    }
}

// ---------------------------------------------------------------------------
// Kernel 2: weight matrix prep, K ordered (tap, q, ci), tf32-rounded
// ---------------------------------------------------------------------------
__global__ void bprep_kernel(const float* __restrict__ w) {
    int idx = blockIdx.x * blockDim.x + threadIdx.x;
    if (idx >= COUT * KTOT) return;
    int co = idx / KTOT;
    int kk = idx % KTOT;
    int tap = kk / KPT;
    int k2 = kk % KPT;
    int q = k2 >> 6;
    int ci = k2 & 63;
    int ky = tap / 3;
    int kx = tap % 3;
    g_B[idx] = round_tf32(
        w[(((size_t)co * (3 * CIN) + q * CIN + ci) * 3 + ky) * 3 + kx]);
}

// ---------------------------------------------------------------------------
// Kernel 3: implicit-GEMM conv via mma.sync tf32 (HMMA).
// CTA: 128(M) x 128(N) x K-chunks of 16, 3-stage cp.async pipeline.
// 8 warps as 2(M) x 4(N); warp tile 64x32 (4 mtiles x 4 ntiles of m16n8).
// ---------------------------------------------------------------------------
__global__ void __launch_bounds__(256, 2)
gemm_kernel(const float* __restrict__ bias, float* __restrict__ out) {
    extern __shared__ float smem[];
    const uint32_t sbase = smem_u32(smem);
    const int tid = threadIdx.x;
    const int lane = tid & 31;
    const int wid = tid >> 5;
    const long long m0 = (long long)blockIdx.x * 128;

    const int warpM = (wid >> 2) * 64;
    const int warpN = (wid & 3) * 32;

    // ldmatrix per-thread source coordinates
    const int rowA = ((lane >> 3) & 1) * 8 + (lane & 7);
    const int colA = (lane >> 4) * 4;
    const uint32_t aAddr0 = sbase + (uint32_t)(((warpM + rowA) * PITCH + colA) * 4);
    const int rowB = lane & 7;
    const int colB = ((lane >> 3) & 1) * 4;
    const uint32_t bAddr0 =
        sbase + (uint32_t)(TILE_F * 4) + (uint32_t)(((warpN + rowB) * PITCH + colB) * 4);

    // cp.async per-thread coordinates: 2 ids cover 512 16B-chunks per tile
    const int r0 = tid >> 2, kc0 = tid & 3;
    const int r1 = (tid + 256) >> 2, kc1 = tid & 3;

    float acc[4][4][4];
#pragma unroll
    for (int i = 0; i < 4; ++i)
#pragma unroll
        for (int j = 0; j < 4; ++j)
#pragma unroll
            for (int k = 0; k < 4; ++k) acc[i][j][k] = 0.f;

    // -------- stage loader --------
    auto load_chunk = [&](int c, int s) {
        const int tap = c / 12;
        const int inner = (c % 12) * 16;
        const int toff = (tap / 3 - 1) * HP + (tap % 3 - 1);
        const uint32_t dA = sbase + (uint32_t)(s * STAGE_F * 4);
        const uint32_t dB = dA + (uint32_t)(TILE_F * 4);

        {
            long long grow = m0 + r0 + toff;
            bool ok = (grow >= 0) && (grow < (long long)MPAD);
            const float* src = g_P + (ok ? grow : 0) * KPT + inner + kc0 * 4;
            cp16(dA + (uint32_t)((r0 * PITCH + kc0 * 4) * 4), src, ok ? 16u : 0u);
            cp16(dB + (uint32_t)((r0 * PITCH + kc0 * 4) * 4),
                 g_B + (size_t)r0 * KTOT + c * 16 + kc0 * 4, 16u);
        }
        {
            long long grow = m0 + r1 + toff;
            bool ok = (grow >= 0) && (grow < (long long)MPAD);
            const float* src = g_P + (ok ? grow : 0) * KPT + inner + kc1 * 4;
            cp16(dA + (uint32_t)((r1 * PITCH + kc1 * 4) * 4), src, ok ? 16u : 0u);
            cp16(dB + (uint32_t)((r1 * PITCH + kc1 * 4) * 4),
                 g_B + (size_t)r1 * KTOT + c * 16 + kc1 * 4, 16u);
        }
        CP_COMMIT();
    };

    // prologue: stages 0..1
#pragma unroll
    for (int s = 0; s < STAGES - 1; ++s) load_chunk(s, s);

    // -------- main loop --------
#pragma unroll 1
    for (int c = 0; c < NCHUNK; ++c) {
        const int cpre = c + STAGES - 1;
        if (cpre < NCHUNK) load_chunk(cpre, cpre % STAGES);
        else CP_COMMIT();
        CP_WAIT1();
        __syncthreads();

        const uint32_t soff = (uint32_t)((c % STAGES) * STAGE_F * 4);
        const uint32_t sa = aAddr0 + soff;
        const uint32_t sb = bAddr0 + soff;

#pragma unroll
        for (int ks = 0; ks < 2; ++ks) {
            const uint32_t koff = (uint32_t)(ks * 8 * 4);
            uint32_t b0[4], b1[4];
#pragma unroll
            for (int nt = 0; nt < 4; ++nt)
                LDSM_X2(b0[nt], b1[nt], sb + (uint32_t)(nt * 8 * PITCH * 4) + koff);
#pragma unroll
            for (int mt = 0; mt < 4; ++mt) {
                uint32_t a0, a1, a2, a3;
                LDSM_X4(a0, a1, a2, a3, sa + (uint32_t)(mt * 16 * PITCH * 4) + koff);
#pragma unroll
                for (int nt = 0; nt < 4; ++nt)
                    MMA_TF32(acc[mt][nt], a0, a1, a2, a3, b0[nt], b1[nt]);
            }
        }
        __syncthreads();
    }

    // -------- epilogue --------
    float bv[4][2];
#pragma unroll
    for (int nt = 0; nt < 4; ++nt) {
        int co = warpN + nt * 8 + 2 * (lane & 3);
        bv[nt][0] = bias[co];
        bv[nt][1] = bias[co + 1];
    }

#pragma unroll
    for (int mt = 0; mt < 4; ++mt) {
#pragma unroll
        for (int half = 0; half < 2; ++half) {
            long long m = m0 + warpM + mt * 16 + (lane >> 2) + half * 8;
            if (m >= (long long)MPAD) continue;
            int mi = (int)m;
            int nb = mi / HP2;
            int rem = mi % HP2;
            int hp = rem / HP;
            int wp = rem % HP;
            if (hp < 1 || hp > HH || wp < 1 || wp > WW) continue;
            float* op = out + (((size_t)nb * COUT) * HH + (hp - 1)) * WW + (wp - 1);
#pragma unroll
            for (int nt = 0; nt < 4; ++nt) {
                int co = warpN + nt * 8 + 2 * (lane & 3);
                op[(size_t)co * (HH * WW)] = acc[mt][nt][half * 2 + 0] + bv[nt][0];
                op[(size_t)(co + 1) * (HH * WW)] = acc[mt][nt][half * 2 + 1] + bv[nt][1];
            }
        }
    }
}

// ---------------------------------------------------------------------------
extern "C" void kernel_launch(void* const* d_in, const int* in_sizes, int n_in,
                              void* d_out, int out_size) {
    const float* x = (const float*)d_in[0];
    const float* weights = (const float*)d_in[1];
    const float* bias = (const float*)d_in[2];
    const float* shifts = (const float*)d_in[3];
    float* out = (float*)d_out;

    pbuild_kernel<<<NB * HP, 256>>>(x, shifts);
    bprep_kernel<<<(COUT * KTOT + 255) / 256, 256>>>(weights);

    cudaFuncSetAttribute(gemm_kernel,
                         cudaFuncAttributeMaxDynamicSharedMemorySize,
                         SMEM_BYTES);
    const int grid = (MPAD + 127) / 128;  // 1625
    gemm_kernel<<<grid, 256, SMEM_BYTES>>>(bias, out);
}